// round 13
// baseline (speedup 1.0000x reference)
#include <cuda_runtime.h>
#include <cuda_bf16.h>
#include <cstdint>

// ---------------- problem constants ----------------
#define BB 4
#define HH 128
#define HID 7168
#define QL 1536
#define KVL 512
#define DN 128
#define DR 64
#define DV 128
#define DQK 192
#define TT 1025          // PAST + 1
#define TTP 1028         // padded t-stride for g_ct (16B alignment)
#define QROWS (HH*DQK)   // 24576
#define CTXD (HH*DV)     // 16384
#define QFD 576          // KVL + DR
#define NSPLIT 4
#define SCP2 260
// 1/sqrt(192)
#define SCALE_QK 0.07216878364870323f

// ---------------- device scratch ----------------
__device__ float g_qa[BB*QL];
__device__ float g_qan[BB*QL];
__device__ float g_q[BB*QROWS];
__device__ float g_ckv[BB*QFD];
__device__ float g_qfull[BB*HH*QFD];
__device__ float g_ctx[BB*CTXD];
__device__ float g_ct[(size_t)BB*QFD*TTP];    // transposed cache [b][k][t], padded
__device__ float g_pm[BB*HH*NSPLIT];
__device__ float g_ps[BB*HH*NSPLIT];
__device__ float g_pctx[(size_t)BB*HH*NSPLIT*KVL];

__device__ __forceinline__ int get_pos(const int* __restrict__ p, int b)
{
    bool is64 = (p[1] == 0) && (p[3] == 0) && (p[0] != 0);
    return is64 ? p[2*b] : p[b];
}

// ---------------- GEMV core: RW=2,U=4, smem-staged X, 8-deep LDG batch ----------------
__device__ __forceinline__ void gemv_core(const float4* __restrict__ arow0,
                                          const float4* __restrict__ arow1,
                                          const float4* __restrict__ X,
                                          float4 (*sx)[512],
                                          int K4, float acc[2][4])
{
    int tid = threadIdx.x, lane = tid & 31;
    for (int kt = 0; kt < K4; kt += 512) {
        int cur = min(512, K4 - kt);
        __syncthreads();
        for (int i = tid; i < cur; i += 256) {
            sx[0][i] = X[(size_t)0*K4 + kt + i];
            sx[1][i] = X[(size_t)1*K4 + kt + i];
            sx[2][i] = X[(size_t)2*K4 + kt + i];
            sx[3][i] = X[(size_t)3*K4 + kt + i];
        }
        __syncthreads();
        for (int ib = 0; ib < cur; ib += 128) {
            float4 av[4][2];
            #pragma unroll
            for (int u = 0; u < 4; u++) {
                av[u][0] = arow0[kt + ib + u*32 + lane];
                av[u][1] = arow1[kt + ib + u*32 + lane];
            }
            #pragma unroll
            for (int u = 0; u < 4; u++) {
                #pragma unroll
                for (int b = 0; b < 4; b++) {
                    float4 xv = sx[b][ib + u*32 + lane];
                    acc[0][b] += av[u][0].x*xv.x + av[u][0].y*xv.y
                               + av[u][0].z*xv.z + av[u][0].w*xv.w;
                    acc[1][b] += av[u][1].x*xv.x + av[u][1].y*xv.y
                               + av[u][1].z*xv.z + av[u][1].w*xv.w;
                }
            }
        }
    }
    #pragma unroll
    for (int r = 0; r < 2; r++)
        #pragma unroll
        for (int b = 0; b < 4; b++)
            #pragma unroll
            for (int off = 16; off; off >>= 1)
                acc[r][b] += __shfl_xor_sync(0xffffffffu, acc[r][b], off);
}

__global__ __launch_bounds__(256, 5)
void gemv3_kernel(const float4* __restrict__ A, const float4* __restrict__ X,
                  float* __restrict__ out, int K4, int outStride)
{
    __shared__ float4 sx[4][512];
    int tid = threadIdx.x, w = tid >> 5, lane = tid & 31;
    int row0 = (blockIdx.x * 8 + w) * 2;
    float acc[2][4] = {{0,0,0,0},{0,0,0,0}};
    gemv_core(A + (size_t)row0*K4, A + (size_t)(row0+1)*K4, X, sx, K4, acc);
    if (lane == 0) {
        #pragma unroll
        for (int r = 0; r < 2; r++)
            #pragma unroll
            for (int b = 0; b < 4; b++)
                out[(size_t)b*outStride + row0 + r] = acc[r][b];
    }
}

// dual: rows [0,QL) -> A1/out1, rows [QL,QL+QFD) -> A2/out2 (same X, same K4)
__global__ __launch_bounds__(256, 5)
void gemv3_dual_kernel(const float4* __restrict__ A1, const float4* __restrict__ A2,
                       const float4* __restrict__ X,
                       float* __restrict__ out1, float* __restrict__ out2, int K4)
{
    __shared__ float4 sx[4][512];
    int tid = threadIdx.x, w = tid >> 5, lane = tid & 31;
    int row0 = (blockIdx.x * 8 + w) * 2;
    const float4* A;
    float* out;
    int outStride, rbase;
    if (row0 < QL) { A = A1; out = out1; outStride = QL; rbase = row0; }
    else           { A = A2; out = out2; outStride = QFD; rbase = row0 - QL; }
    float acc[2][4] = {{0,0,0,0},{0,0,0,0}};
    gemv_core(A + (size_t)rbase*K4, A + (size_t)(rbase+1)*K4, X, sx, K4, acc);
    if (lane == 0) {
        #pragma unroll
        for (int r = 0; r < 2; r++)
            #pragma unroll
            for (int b = 0; b < 4; b++)
                out[(size_t)b*outStride + rbase + r] = acc[r][b];
    }
}

// ---------------- rmsnorm of q_a ----------------
__global__ void rmsnorm_q_kernel(const float* __restrict__ gamma)
{
    int b = blockIdx.x, tid = threadIdx.x;
    float ss = 0.f;
    for (int i = tid; i < QL; i += 256) { float v = g_qa[b*QL+i]; ss += v*v; }
    #pragma unroll
    for (int off = 16; off; off >>= 1) ss += __shfl_xor_sync(0xffffffffu, ss, off);
    __shared__ float r[8];
    __shared__ float s_rs;
    if ((tid & 31) == 0) r[tid >> 5] = ss;
    __syncthreads();
    if (tid == 0) {
        float t = 0.f;
        #pragma unroll
        for (int i = 0; i < 8; i++) t += r[i];
        s_rs = rsqrtf(t / (float)QL + 1e-6f);
    }
    __syncthreads();
    for (int i = tid; i < QL; i += 256) g_qan[b*QL+i] = g_qa[b*QL+i] * s_rs * gamma[i];
}

// ---------------- fused prep v3: transpose+copy in one pass | ckv_post ----------------
// transpose blocks ALSO write the straight copy to out_cache (single past read).
// 16 t-tiles * 9 k-tiles * 4 b = 576 blocks + BB ckv blocks.
#define PREP_TRANS 576
__global__ void prep_kernel(const float* __restrict__ past,
                            float* __restrict__ out_cache,
                            const float* __restrict__ gkv, const float* __restrict__ cosT,
                            const float* __restrict__ sinT, const int* __restrict__ posw)
{
    __shared__ float tile[64][68];
    int blk = blockIdx.x, tid = threadIdx.x;

    if (blk < PREP_TRANS) {
        int b = blk / 144, rem = blk % 144;
        int kb = (rem / 16) * 64, tb = (rem % 16) * 64;
        int tx = tid & 15, ty = tid >> 4;   // 16 x 16
        #pragma unroll
        for (int j = 0; j < 4; j++) {
            int t = tb + ty + 16*j;
            float4 v = *(const float4*)&past[((size_t)b*(TT-1) + t)*QFD + kb + tx*4];
            *(float4*)&tile[ty + 16*j][tx*4] = v;
            *(float4*)&out_cache[((size_t)b*TT + t)*QFD + kb + tx*4] = v;   // fused copy
        }
        __syncthreads();
        #pragma unroll
        for (int j = 0; j < 4; j++) {
            int k = ty + 16*j;
            float4 o;
            o.x = tile[tx*4+0][k];
            o.y = tile[tx*4+1][k];
            o.z = tile[tx*4+2][k];
            o.w = tile[tx*4+3][k];
            *(float4*)&g_ct[((size_t)b*QFD + kb + k)*TTP + tb + tx*4] = o;
        }
        return;
    }
    {
        int b = blk - PREP_TRANS;
        float* red = (float*)tile;        // reuse smem
        float* prs = (float*)tile + 8;
        const float* cv = g_ckv + b*QFD;
        float ss = 0.f;
        for (int i = tid; i < KVL; i += 256) { float v = cv[i]; ss += v*v; }
        #pragma unroll
        for (int off = 16; off; off >>= 1) ss += __shfl_xor_sync(0xffffffffu, ss, off);
        if ((tid & 31) == 0) red[tid >> 5] = ss;
        __syncthreads();
        if (tid == 0) {
            float t = 0.f;
            #pragma unroll
            for (int i = 0; i < 8; i++) t += red[i];
            *prs = rsqrtf(t / (float)KVL + 1e-6f);
        }
        __syncthreads();
        float s_rs = *prs;
        float* dst = out_cache + ((size_t)b*TT + (TT-1)) * QFD;
        float* ctb = g_ct + (size_t)b*QFD*TTP + (TT-1);
        for (int i = tid; i < KVL; i += 256) {
            float v = cv[i] * s_rs * gkv[i];
            dst[i] = v;
            ctb[(size_t)i*TTP] = v;
        }
        if (tid < DR) {
            int d = tid;
            int p = get_pos(posw, b);
            float v  = cv[KVL + d];
            float pr = (d < 32) ? -cv[KVL + d + 32] : cv[KVL + d - 32];
            float res = v * cosT[(size_t)p*DR + d] + pr * sinT[(size_t)p*DR + d];
            dst[KVL + d] = res;
            ctb[(size_t)(KVL + d)*TTP] = res;
        }
    }
}

// ---------------- absorption v3: float4 columns, d-split halves ----------------
__global__ __launch_bounds__(256)
void absorb_rope_kernel(const float* __restrict__ w_kvb,
                        const float* __restrict__ cosT, const float* __restrict__ sinT,
                        const int* __restrict__ posw)
{
    int h = blockIdx.x, tid = threadIdx.x;
    int c4 = tid & 127, dh = tid >> 7;
    __shared__ float qs[4][DN];
    __shared__ float4 sred[4][128];     // half-1 partials, 8KB
    for (int i = tid; i < 4*DN; i += 256) {
        int b = i >> 7, d = i & 127;
        qs[b][d] = g_q[(size_t)b*QROWS + h*DQK + d];
    }
    __syncthreads();
    float4 acc[4];
    #pragma unroll
    for (int b = 0; b < 4; b++) acc[b] = make_float4(0.f, 0.f, 0.f, 0.f);
    const float4* wk4 = (const float4*)(w_kvb + (size_t)h*256*KVL) + c4;  // row stride 128 f4
    int d0base = dh * 64;
    for (int d0 = d0base; d0 < d0base + 64; d0 += 8) {
        float4 wv[8];
        #pragma unroll
        for (int u = 0; u < 8; u++) wv[u] = wk4[(size_t)(d0+u)*128];
        #pragma unroll
        for (int u = 0; u < 8; u++) {
            #pragma unroll
            for (int b = 0; b < 4; b++) {
                float q = qs[b][d0+u];
                acc[b].x += q*wv[u].x; acc[b].y += q*wv[u].y;
                acc[b].z += q*wv[u].z; acc[b].w += q*wv[u].w;
            }
        }
    }
    if (dh == 1) {
        #pragma unroll
        for (int b = 0; b < 4; b++) sred[b][c4] = acc[b];
    }
    __syncthreads();
    if (dh == 0) {
        #pragma unroll
        for (int b = 0; b < 4; b++) {
            float4 o = sred[b][c4];
            o.x = (acc[b].x + o.x) * SCALE_QK;
            o.y = (acc[b].y + o.y) * SCALE_QK;
            o.z = (acc[b].z + o.z) * SCALE_QK;
            o.w = (acc[b].w + o.w) * SCALE_QK;
            *(float4*)&g_qfull[((size_t)(b*HH + h))*QFD + c4*4] = o;
        }
    }
    // RoPE for q_pe: 4 b * 64 d = 256 values
    if (tid < 4*DR) {
        int b = tid >> 6, d = tid & 63;
        int p = get_pos(posw, b);
        const float* qp = g_q + (size_t)b*QROWS + h*DQK + DN;
        float v  = qp[d];
        float pr = (d < 32) ? -qp[d+32] : qp[d-32];
        g_qfull[((size_t)(b*HH + h))*QFD + KVL + d] =
            (v * cosT[(size_t)p*DR + d] + pr * sinT[(size_t)p*DR + d]) * SCALE_QK;
    }
}

// ---------------- attention split, 512 threads ----------------
__global__ __launch_bounds__(512)
void attn_split_kernel(const float* __restrict__ past,
                       const float* __restrict__ out_cache,
                       const float* __restrict__ mask)
{
    __shared__ __align__(16) float qsm[8*QFD];
    __shared__ __align__(16) float sc[8*SCP2];
    int b = blockIdx.z, split = blockIdx.y, h0 = blockIdx.x * 8, tid = threadIdx.x;
    int T0 = split * 256;
    int TE = (split == NSPLIT-1) ? TT : T0 + 256;
    int cnt = TE - T0;

    for (int i = tid; i < 8*QFD; i += 512) {
        int h = i / QFD, k = i % QFD;
        qsm[i] = g_qfull[((size_t)(b*HH + h0 + h))*QFD + k];
    }
    __syncthreads();

    // ---- phase 1: scores; half-block does 4 heads each for t = T0 + (tid&255) ----
    {
        int tq = tid & 255;
        int hb = (tid >> 8) * 4;
        float acc[4] = {0.f, 0.f, 0.f, 0.f};
        const float* ctb = g_ct + (size_t)b*QFD*TTP + T0 + tq;
        for (int k = 0; k < QFD; k += 8) {
            float c[8];
            #pragma unroll
            for (int j = 0; j < 8; j++) c[j] = ctb[(size_t)(k+j)*TTP];
            #pragma unroll
            for (int hh = 0; hh < 4; hh++) {
                const float4* qv = reinterpret_cast<const float4*>(&qsm[(hb+hh)*QFD + k]);
                float4 q0 = qv[0], q1 = qv[1];
                acc[hh] += q0.x*c[0] + q0.y*c[1] + q0.z*c[2] + q0.w*c[3]
                         + q1.x*c[4] + q1.y*c[5] + q1.z*c[6] + q1.w*c[7];
            }
        }
        float mk = mask[(size_t)b*TT + T0 + tq];
        #pragma unroll
        for (int hh = 0; hh < 4; hh++) sc[(hb+hh)*SCP2 + tq] = acc[hh] + mk;

        if (split == NSPLIT-1 && tid < 32) {   // t = 1024 by warp 0
            const float* crow = out_cache + ((size_t)b*TT + (TT-1))*QFD;
            float mk2 = mask[(size_t)b*TT + (TT-1)];
            for (int h = 0; h < 8; h++) {
                float p = 0.f;
                for (int i = tid; i < QFD; i += 32) p += qsm[h*QFD + i]*crow[i];
                #pragma unroll
                for (int off = 16; off; off >>= 1) p += __shfl_xor_sync(0xffffffffu, p, off);
                if (tid == 0) sc[h*SCP2 + 256] = p + mk2;
            }
        }
    }
    __syncthreads();

    // ---- phase 2: local softmax, warps 0-7 (one per head) ----
    if (tid < 256) {
        int w = tid >> 5, lane = tid & 31, h = w;
        float m = -1e30f;
        for (int t = lane; t < cnt; t += 32) m = fmaxf(m, sc[h*SCP2 + t]);
        #pragma unroll
        for (int off = 16; off; off >>= 1) m = fmaxf(m, __shfl_xor_sync(0xffffffffu, m, off));
        float s = 0.f;
        for (int t = lane; t < cnt; t += 32) {
            float e = __expf(sc[h*SCP2 + t] - m);
            sc[h*SCP2 + t] = e;
            s += e;
        }
        #pragma unroll
        for (int off = 16; off; off >>= 1) s += __shfl_xor_sync(0xffffffffu, s, off);
        if (lane == 0) {
            int idx = (b*HH + h0 + h)*NSPLIT + split;
            g_pm[idx] = m;
            g_ps[idx] = s;
        }
    }
    __syncthreads();

    // ---- phase 3: partial ctx; each thread owns latent column c = tid ----
    {
        float acc[8];
        #pragma unroll
        for (int h = 0; h < 8; h++) acc[h] = 0.f;
        const float* pb = past + (size_t)b*(TT-1)*QFD;
        int c = tid;
        for (int t0 = T0; t0 < T0 + 256; t0 += 4) {
            float v[4];
            #pragma unroll
            for (int j = 0; j < 4; j++) v[j] = pb[(size_t)(t0+j)*QFD + c];
            int tl = t0 - T0;
            #pragma unroll
            for (int h = 0; h < 8; h++) {
                float4 a4 = *reinterpret_cast<const float4*>(&sc[h*SCP2 + tl]);
                acc[h] += a4.x*v[0] + a4.y*v[1] + a4.z*v[2] + a4.w*v[3];
            }
        }
        if (TE == TT) {
            float v = out_cache[((size_t)b*TT + (TT-1))*QFD + c];
            #pragma unroll
            for (int h = 0; h < 8; h++) acc[h] += sc[h*SCP2 + 256] * v;
        }
        #pragma unroll
        for (int h = 0; h < 8; h++)
            g_pctx[((size_t)(b*HH + h0 + h)*NSPLIT + split)*KVL + c] = acc[h];
    }
}

// ---------------- fused combine + V projection; grid (HH, 2) ----------------
__global__ void vproj_combine_kernel(const float* __restrict__ w_kvb)
{
    __shared__ float cl[4][KVL];
    int h = blockIdx.x, half = blockIdx.y, tid = threadIdx.x;
    {
        int bq = tid >> 6, lq = tid & 63;
        int idx = bq*HH + h;
        float m = -1e30f;
        #pragma unroll
        for (int s = 0; s < NSPLIT; s++) m = fmaxf(m, g_pm[idx*NSPLIT + s]);
        float e[NSPLIT]; float ssum = 0.f;
        #pragma unroll
        for (int s = 0; s < NSPLIT; s++) {
            e[s] = __expf(g_pm[idx*NSPLIT + s] - m);
            ssum += g_ps[idx*NSPLIT + s] * e[s];
        }
        float inv = 1.0f / ssum;
        for (int c = lq; c < KVL; c += 64) {
            float acc = 0.f;
            #pragma unroll
            for (int s = 0; s < NSPLIT; s++)
                acc += g_pctx[((size_t)idx*NSPLIT + s)*KVL + c] * e[s];
            cl[bq][c] = acc * inv;
        }
    }
    __syncthreads();
    int w = tid >> 5, lane = tid & 31;
    int dv = half*64 + w*8;
    for (int d = dv; d < dv + 8; d++) {
        const float* wr = w_kvb + ((size_t)(h*256 + DN + d))*KVL;
        float p0 = 0.f, p1 = 0.f, p2 = 0.f, p3 = 0.f;
        #pragma unroll 4
        for (int i = lane; i < KVL; i += 32) {
            float wv = wr[i];
            p0 += wv * cl[0][i];
            p1 += wv * cl[1][i];
            p2 += wv * cl[2][i];
            p3 += wv * cl[3][i];
        }
        #pragma unroll
        for (int off = 16; off; off >>= 1) {
            p0 += __shfl_xor_sync(0xffffffffu, p0, off);
            p1 += __shfl_xor_sync(0xffffffffu, p1, off);
            p2 += __shfl_xor_sync(0xffffffffu, p2, off);
            p3 += __shfl_xor_sync(0xffffffffu, p3, off);
        }
        if (lane == 0) {
            g_ctx[(size_t)0*CTXD + h*DV + d] = p0;
            g_ctx[(size_t)1*CTXD + h*DV + d] = p1;
            g_ctx[(size_t)2*CTXD + h*DV + d] = p2;
            g_ctx[(size_t)3*CTXD + h*DV + d] = p3;
        }
    }
}

// ---------------- host launch (single stream, zero allocations) ----------------
extern "C" void kernel_launch(void* const* d_in, const int* in_sizes, int n_in,
                              void* d_out, int out_size)
{
    const float* x      = (const float*)d_in[0];
    const float* mask   = (const float*)d_in[1];
    const int*   posw   = (const int*)  d_in[2];
    const float* past   = (const float*)d_in[3];
    const float* cosT   = (const float*)d_in[4];
    const float* sinT   = (const float*)d_in[5];
    const float* w_qa   = (const float*)d_in[6];
    const float* gq     = (const float*)d_in[7];
    const float* w_qb   = (const float*)d_in[8];
    const float* w_kva  = (const float*)d_in[9];
    const float* gkv    = (const float*)d_in[10];
    const float* w_kvb  = (const float*)d_in[11];
    const float* w_o    = (const float*)d_in[12];

    float* out_attn  = (float*)d_out;                  // [4,1,7168]
    float* out_cache = out_attn + (size_t)BB*HID;      // [4,1025,576]

    float *p_qa, *p_qan, *p_q, *p_ckv, *p_ctx;
    cudaGetSymbolAddress((void**)&p_qa,  g_qa);
    cudaGetSymbolAddress((void**)&p_qan, g_qan);
    cudaGetSymbolAddress((void**)&p_q,   g_q);
    cudaGetSymbolAddress((void**)&p_ckv, g_ckv);
    cudaGetSymbolAddress((void**)&p_ctx, g_ctx);

    // q_a = x @ w_qa.T  AND  ckv = x @ w_kva.T  (one launch, 132 blocks)
    gemv3_dual_kernel<<<(QL+QFD)/16, 256>>>((const float4*)w_qa, (const float4*)w_kva,
                                            (const float4*)x, p_qa, p_ckv, HID/4);
    // rmsnorm(q_a)
    rmsnorm_q_kernel<<<BB, 256>>>(gq);
    // q = q_an @ w_qb.T        (151 MB, 1536 blocks)
    gemv3_kernel<<<QROWS/16, 256>>>((const float4*)w_qb, (const float4*)p_qan, p_q, QL/4, QROWS);
    // fused prep v3: transpose+copy (single past read) | ckv_post
    prep_kernel<<<PREP_TRANS + BB, 256>>>(past, out_cache, gkv, cosT, sinT, posw);
    // absorption v3 + fused q_pe RoPE
    absorb_rope_kernel<<<HH, 256>>>(w_kvb, cosT, sinT, posw);
    // attention: split-KV, 512 threads
    attn_split_kernel<<<dim3(HH/8, NSPLIT, BB), 512>>>(past, out_cache, mask);
    // combine + V projection
    vproj_combine_kernel<<<dim3(HH, 2), 256>>>(w_kvb);
    // attn_out = ctx @ w_o.T   (470 MB, 448 blocks)
    gemv3_kernel<<<HID/16, 256>>>((const float4*)w_o, (const float4*)p_ctx, out_attn, CTXD/4, HID);
}

// round 14
// speedup vs baseline: 1.1176x; 1.1176x over previous
#include <cuda_runtime.h>
#include <cuda_bf16.h>
#include <cstdint>

// ---------------- problem constants ----------------
#define BB 4
#define HH 128
#define HID 7168
#define QL 1536
#define KVL 512
#define DN 128
#define DR 64
#define DV 128
#define DQK 192
#define TT 1025          // PAST + 1
#define TTP 1028         // padded t-stride for g_ct (16B alignment)
#define QROWS (HH*DQK)   // 24576
#define CTXD (HH*DV)     // 16384
#define QFD 576          // KVL + DR
#define NSPLIT 4
#define SCP2 260
// 1/sqrt(192)
#define SCALE_QK 0.07216878364870323f

// ---------------- device scratch ----------------
__device__ float g_qa[BB*QL];
__device__ float g_qan[BB*QL];
__device__ float g_q[BB*QROWS];
__device__ float g_ckv[BB*QFD];
__device__ float g_qfull[BB*HH*QFD];
__device__ float g_ctx[BB*CTXD];
__device__ float g_ct[(size_t)BB*QFD*TTP];    // transposed cache [b][k][t], padded
__device__ float g_pm[BB*HH*NSPLIT];
__device__ float g_ps[BB*HH*NSPLIT];
__device__ float g_pctx[(size_t)BB*HH*NSPLIT*KVL];

__device__ __forceinline__ int get_pos(const int* __restrict__ p, int b)
{
    bool is64 = (p[1] == 0) && (p[3] == 0) && (p[0] != 0);
    return is64 ? p[2*b] : p[b];
}

// ---------------- GEMV core: RW=2,U=4, smem-staged X, 8-deep LDG batch ----------------
__device__ __forceinline__ void gemv_core(const float4* __restrict__ arow0,
                                          const float4* __restrict__ arow1,
                                          const float4* __restrict__ X,
                                          float4 (*sx)[512],
                                          int K4, float acc[2][4])
{
    int tid = threadIdx.x, lane = tid & 31;
    for (int kt = 0; kt < K4; kt += 512) {
        int cur = min(512, K4 - kt);
        __syncthreads();
        for (int i = tid; i < cur; i += 256) {
            sx[0][i] = X[(size_t)0*K4 + kt + i];
            sx[1][i] = X[(size_t)1*K4 + kt + i];
            sx[2][i] = X[(size_t)2*K4 + kt + i];
            sx[3][i] = X[(size_t)3*K4 + kt + i];
        }
        __syncthreads();
        for (int ib = 0; ib < cur; ib += 128) {
            float4 av[4][2];
            #pragma unroll
            for (int u = 0; u < 4; u++) {
                av[u][0] = arow0[kt + ib + u*32 + lane];
                av[u][1] = arow1[kt + ib + u*32 + lane];
            }
            #pragma unroll
            for (int u = 0; u < 4; u++) {
                #pragma unroll
                for (int b = 0; b < 4; b++) {
                    float4 xv = sx[b][ib + u*32 + lane];
                    acc[0][b] += av[u][0].x*xv.x + av[u][0].y*xv.y
                               + av[u][0].z*xv.z + av[u][0].w*xv.w;
                    acc[1][b] += av[u][1].x*xv.x + av[u][1].y*xv.y
                               + av[u][1].z*xv.z + av[u][1].w*xv.w;
                }
            }
        }
    }
    #pragma unroll
    for (int r = 0; r < 2; r++)
        #pragma unroll
        for (int b = 0; b < 4; b++)
            #pragma unroll
            for (int off = 16; off; off >>= 1)
                acc[r][b] += __shfl_xor_sync(0xffffffffu, acc[r][b], off);
}

__global__ __launch_bounds__(256, 4)
void gemv3_kernel(const float4* __restrict__ A, const float4* __restrict__ X,
                  float* __restrict__ out, int K4, int outStride)
{
    __shared__ float4 sx[4][512];
    int tid = threadIdx.x, w = tid >> 5, lane = tid & 31;
    int row0 = (blockIdx.x * 8 + w) * 2;
    float acc[2][4] = {{0,0,0,0},{0,0,0,0}};
    gemv_core(A + (size_t)row0*K4, A + (size_t)(row0+1)*K4, X, sx, K4, acc);
    if (lane == 0) {
        #pragma unroll
        for (int r = 0; r < 2; r++)
            #pragma unroll
            for (int b = 0; b < 4; b++)
                out[(size_t)b*outStride + row0 + r] = acc[r][b];
    }
}

// dual: rows [0,QL) -> A1/out1, rows [QL,QL+QFD) -> A2/out2 (same X, same K4)
__global__ __launch_bounds__(256, 4)
void gemv3_dual_kernel(const float4* __restrict__ A1, const float4* __restrict__ A2,
                       const float4* __restrict__ X,
                       float* __restrict__ out1, float* __restrict__ out2, int K4)
{
    __shared__ float4 sx[4][512];
    int tid = threadIdx.x, w = tid >> 5, lane = tid & 31;
    int row0 = (blockIdx.x * 8 + w) * 2;
    const float4* A;
    float* out;
    int outStride, rbase;
    if (row0 < QL) { A = A1; out = out1; outStride = QL; rbase = row0; }
    else           { A = A2; out = out2; outStride = QFD; rbase = row0 - QL; }
    float acc[2][4] = {{0,0,0,0},{0,0,0,0}};
    gemv_core(A + (size_t)rbase*K4, A + (size_t)(rbase+1)*K4, X, sx, K4, acc);
    if (lane == 0) {
        #pragma unroll
        for (int r = 0; r < 2; r++)
            #pragma unroll
            for (int b = 0; b < 4; b++)
                out[(size_t)b*outStride + rbase + r] = acc[r][b];
    }
}

// ---------------- rmsnorm of q_a ----------------
__global__ void rmsnorm_q_kernel(const float* __restrict__ gamma)
{
    int b = blockIdx.x, tid = threadIdx.x;
    float ss = 0.f;
    for (int i = tid; i < QL; i += 256) { float v = g_qa[b*QL+i]; ss += v*v; }
    #pragma unroll
    for (int off = 16; off; off >>= 1) ss += __shfl_xor_sync(0xffffffffu, ss, off);
    __shared__ float r[8];
    __shared__ float s_rs;
    if ((tid & 31) == 0) r[tid >> 5] = ss;
    __syncthreads();
    if (tid == 0) {
        float t = 0.f;
        #pragma unroll
        for (int i = 0; i < 8; i++) t += r[i];
        s_rs = rsqrtf(t / (float)QL + 1e-6f);
    }
    __syncthreads();
    for (int i = tid; i < QL; i += 256) g_qan[b*QL+i] = g_qa[b*QL+i] * s_rs * gamma[i];
}

// ---------------- fused prep v3: transpose+copy in one pass | ckv_post ----------------
#define PREP_TRANS 576
__global__ void prep_kernel(const float* __restrict__ past,
                            float* __restrict__ out_cache,
                            const float* __restrict__ gkv, const float* __restrict__ cosT,
                            const float* __restrict__ sinT, const int* __restrict__ posw)
{
    __shared__ float tile[64][68];
    int blk = blockIdx.x, tid = threadIdx.x;

    if (blk < PREP_TRANS) {
        int b = blk / 144, rem = blk % 144;
        int kb = (rem / 16) * 64, tb = (rem % 16) * 64;
        int tx = tid & 15, ty = tid >> 4;   // 16 x 16
        #pragma unroll
        for (int j = 0; j < 4; j++) {
            int t = tb + ty + 16*j;
            float4 v = *(const float4*)&past[((size_t)b*(TT-1) + t)*QFD + kb + tx*4];
            *(float4*)&tile[ty + 16*j][tx*4] = v;
            *(float4*)&out_cache[((size_t)b*TT + t)*QFD + kb + tx*4] = v;   // fused copy
        }
        __syncthreads();
        #pragma unroll
        for (int j = 0; j < 4; j++) {
            int k = ty + 16*j;
            float4 o;
            o.x = tile[tx*4+0][k];
            o.y = tile[tx*4+1][k];
            o.z = tile[tx*4+2][k];
            o.w = tile[tx*4+3][k];
            *(float4*)&g_ct[((size_t)b*QFD + kb + k)*TTP + tb + tx*4] = o;
        }
        return;
    }
    {
        int b = blk - PREP_TRANS;
        float* red = (float*)tile;        // reuse smem
        float* prs = (float*)tile + 8;
        const float* cv = g_ckv + b*QFD;
        float ss = 0.f;
        for (int i = tid; i < KVL; i += 256) { float v = cv[i]; ss += v*v; }
        #pragma unroll
        for (int off = 16; off; off >>= 1) ss += __shfl_xor_sync(0xffffffffu, ss, off);
        if ((tid & 31) == 0) red[tid >> 5] = ss;
        __syncthreads();
        if (tid == 0) {
            float t = 0.f;
            #pragma unroll
            for (int i = 0; i < 8; i++) t += red[i];
            *prs = rsqrtf(t / (float)KVL + 1e-6f);
        }
        __syncthreads();
        float s_rs = *prs;
        float* dst = out_cache + ((size_t)b*TT + (TT-1)) * QFD;
        float* ctb = g_ct + (size_t)b*QFD*TTP + (TT-1);
        for (int i = tid; i < KVL; i += 256) {
            float v = cv[i] * s_rs * gkv[i];
            dst[i] = v;
            ctb[(size_t)i*TTP] = v;
        }
        if (tid < DR) {
            int d = tid;
            int p = get_pos(posw, b);
            float v  = cv[KVL + d];
            float pr = (d < 32) ? -cv[KVL + d + 32] : cv[KVL + d - 32];
            float res = v * cosT[(size_t)p*DR + d] + pr * sinT[(size_t)p*DR + d];
            dst[KVL + d] = res;
            ctb[(size_t)(KVL + d)*TTP] = res;
        }
    }
}

// ---------------- absorption v3: float4 columns, d-split halves ----------------
__global__ __launch_bounds__(256)
void absorb_rope_kernel(const float* __restrict__ w_kvb,
                        const float* __restrict__ cosT, const float* __restrict__ sinT,
                        const int* __restrict__ posw)
{
    int h = blockIdx.x, tid = threadIdx.x;
    int c4 = tid & 127, dh = tid >> 7;
    __shared__ float qs[4][DN];
    __shared__ float4 sred[4][128];     // half-1 partials, 8KB
    for (int i = tid; i < 4*DN; i += 256) {
        int b = i >> 7, d = i & 127;
        qs[b][d] = g_q[(size_t)b*QROWS + h*DQK + d];
    }
    __syncthreads();
    float4 acc[4];
    #pragma unroll
    for (int b = 0; b < 4; b++) acc[b] = make_float4(0.f, 0.f, 0.f, 0.f);
    const float4* wk4 = (const float4*)(w_kvb + (size_t)h*256*KVL) + c4;  // row stride 128 f4
    int d0base = dh * 64;
    for (int d0 = d0base; d0 < d0base + 64; d0 += 8) {
        float4 wv[8];
        #pragma unroll
        for (int u = 0; u < 8; u++) wv[u] = wk4[(size_t)(d0+u)*128];
        #pragma unroll
        for (int u = 0; u < 8; u++) {
            #pragma unroll
            for (int b = 0; b < 4; b++) {
                float q = qs[b][d0+u];
                acc[b].x += q*wv[u].x; acc[b].y += q*wv[u].y;
                acc[b].z += q*wv[u].z; acc[b].w += q*wv[u].w;
            }
        }
    }
    if (dh == 1) {
        #pragma unroll
        for (int b = 0; b < 4; b++) sred[b][c4] = acc[b];
    }
    __syncthreads();
    if (dh == 0) {
        #pragma unroll
        for (int b = 0; b < 4; b++) {
            float4 o = sred[b][c4];
            o.x = (acc[b].x + o.x) * SCALE_QK;
            o.y = (acc[b].y + o.y) * SCALE_QK;
            o.z = (acc[b].z + o.z) * SCALE_QK;
            o.w = (acc[b].w + o.w) * SCALE_QK;
            *(float4*)&g_qfull[((size_t)(b*HH + h))*QFD + c4*4] = o;
        }
    }
    // RoPE for q_pe: 4 b * 64 d = 256 values
    if (tid < 4*DR) {
        int b = tid >> 6, d = tid & 63;
        int p = get_pos(posw, b);
        const float* qp = g_q + (size_t)b*QROWS + h*DQK + DN;
        float v  = qp[d];
        float pr = (d < 32) ? -qp[d+32] : qp[d-32];
        g_qfull[((size_t)(b*HH + h))*QFD + KVL + d] =
            (v * cosT[(size_t)p*DR + d] + pr * sinT[(size_t)p*DR + d]) * SCALE_QK;
    }
}

// ---------------- attention split, 512 threads ----------------
__global__ __launch_bounds__(512)
void attn_split_kernel(const float* __restrict__ past,
                       const float* __restrict__ out_cache,
                       const float* __restrict__ mask)
{
    __shared__ __align__(16) float qsm[8*QFD];
    __shared__ __align__(16) float sc[8*SCP2];
    int b = blockIdx.z, split = blockIdx.y, h0 = blockIdx.x * 8, tid = threadIdx.x;
    int T0 = split * 256;
    int TE = (split == NSPLIT-1) ? TT : T0 + 256;
    int cnt = TE - T0;

    for (int i = tid; i < 8*QFD; i += 512) {
        int h = i / QFD, k = i % QFD;
        qsm[i] = g_qfull[((size_t)(b*HH + h0 + h))*QFD + k];
    }
    __syncthreads();

    // ---- phase 1: scores; half-block does 4 heads each for t = T0 + (tid&255) ----
    {
        int tq = tid & 255;
        int hb = (tid >> 8) * 4;
        float acc[4] = {0.f, 0.f, 0.f, 0.f};
        const float* ctb = g_ct + (size_t)b*QFD*TTP + T0 + tq;
        for (int k = 0; k < QFD; k += 8) {
            float c[8];
            #pragma unroll
            for (int j = 0; j < 8; j++) c[j] = ctb[(size_t)(k+j)*TTP];
            #pragma unroll
            for (int hh = 0; hh < 4; hh++) {
                const float4* qv = reinterpret_cast<const float4*>(&qsm[(hb+hh)*QFD + k]);
                float4 q0 = qv[0], q1 = qv[1];
                acc[hh] += q0.x*c[0] + q0.y*c[1] + q0.z*c[2] + q0.w*c[3]
                         + q1.x*c[4] + q1.y*c[5] + q1.z*c[6] + q1.w*c[7];
            }
        }
        float mk = mask[(size_t)b*TT + T0 + tq];
        #pragma unroll
        for (int hh = 0; hh < 4; hh++) sc[(hb+hh)*SCP2 + tq] = acc[hh] + mk;

        if (split == NSPLIT-1 && tid < 32) {   // t = 1024 by warp 0
            const float* crow = out_cache + ((size_t)b*TT + (TT-1))*QFD;
            float mk2 = mask[(size_t)b*TT + (TT-1)];
            for (int h = 0; h < 8; h++) {
                float p = 0.f;
                for (int i = tid; i < QFD; i += 32) p += qsm[h*QFD + i]*crow[i];
                #pragma unroll
                for (int off = 16; off; off >>= 1) p += __shfl_xor_sync(0xffffffffu, p, off);
                if (tid == 0) sc[h*SCP2 + 256] = p + mk2;
            }
        }
    }
    __syncthreads();

    // ---- phase 2: local softmax, warps 0-7 (one per head) ----
    if (tid < 256) {
        int w = tid >> 5, lane = tid & 31, h = w;
        float m = -1e30f;
        for (int t = lane; t < cnt; t += 32) m = fmaxf(m, sc[h*SCP2 + t]);
        #pragma unroll
        for (int off = 16; off; off >>= 1) m = fmaxf(m, __shfl_xor_sync(0xffffffffu, m, off));
        float s = 0.f;
        for (int t = lane; t < cnt; t += 32) {
            float e = __expf(sc[h*SCP2 + t] - m);
            sc[h*SCP2 + t] = e;
            s += e;
        }
        #pragma unroll
        for (int off = 16; off; off >>= 1) s += __shfl_xor_sync(0xffffffffu, s, off);
        if (lane == 0) {
            int idx = (b*HH + h0 + h)*NSPLIT + split;
            g_pm[idx] = m;
            g_ps[idx] = s;
        }
    }
    __syncthreads();

    // ---- phase 3: partial ctx; each thread owns latent column c = tid ----
    {
        float acc[8];
        #pragma unroll
        for (int h = 0; h < 8; h++) acc[h] = 0.f;
        const float* pb = past + (size_t)b*(TT-1)*QFD;
        int c = tid;
        for (int t0 = T0; t0 < T0 + 256; t0 += 4) {
            float v[4];
            #pragma unroll
            for (int j = 0; j < 4; j++) v[j] = pb[(size_t)(t0+j)*QFD + c];
            int tl = t0 - T0;
            #pragma unroll
            for (int h = 0; h < 8; h++) {
                float4 a4 = *reinterpret_cast<const float4*>(&sc[h*SCP2 + tl]);
                acc[h] += a4.x*v[0] + a4.y*v[1] + a4.z*v[2] + a4.w*v[3];
            }
        }
        if (TE == TT) {
            float v = out_cache[((size_t)b*TT + (TT-1))*QFD + c];
            #pragma unroll
            for (int h = 0; h < 8; h++) acc[h] += sc[h*SCP2 + 256] * v;
        }
        #pragma unroll
        for (int h = 0; h < 8; h++)
            g_pctx[((size_t)(b*HH + h0 + h)*NSPLIT + split)*KVL + c] = acc[h];
    }
}

// ---------------- fused combine + V projection; grid (HH, 2) ----------------
__global__ void vproj_combine_kernel(const float* __restrict__ w_kvb)
{
    __shared__ float cl[4][KVL];
    int h = blockIdx.x, half = blockIdx.y, tid = threadIdx.x;
    {
        int bq = tid >> 6, lq = tid & 63;
        int idx = bq*HH + h;
        float m = -1e30f;
        #pragma unroll
        for (int s = 0; s < NSPLIT; s++) m = fmaxf(m, g_pm[idx*NSPLIT + s]);
        float e[NSPLIT]; float ssum = 0.f;
        #pragma unroll
        for (int s = 0; s < NSPLIT; s++) {
            e[s] = __expf(g_pm[idx*NSPLIT + s] - m);
            ssum += g_ps[idx*NSPLIT + s] * e[s];
        }
        float inv = 1.0f / ssum;
        for (int c = lq; c < KVL; c += 64) {
            float acc = 0.f;
            #pragma unroll
            for (int s = 0; s < NSPLIT; s++)
                acc += g_pctx[((size_t)idx*NSPLIT + s)*KVL + c] * e[s];
            cl[bq][c] = acc * inv;
        }
    }
    __syncthreads();
    int w = tid >> 5, lane = tid & 31;
    int dv = half*64 + w*8;
    for (int d = dv; d < dv + 8; d++) {
        const float* wr = w_kvb + ((size_t)(h*256 + DN + d))*KVL;
        float p0 = 0.f, p1 = 0.f, p2 = 0.f, p3 = 0.f;
        #pragma unroll 4
        for (int i = lane; i < KVL; i += 32) {
            float wv = wr[i];
            p0 += wv * cl[0][i];
            p1 += wv * cl[1][i];
            p2 += wv * cl[2][i];
            p3 += wv * cl[3][i];
        }
        #pragma unroll
        for (int off = 16; off; off >>= 1) {
            p0 += __shfl_xor_sync(0xffffffffu, p0, off);
            p1 += __shfl_xor_sync(0xffffffffu, p1, off);
            p2 += __shfl_xor_sync(0xffffffffu, p2, off);
            p3 += __shfl_xor_sync(0xffffffffu, p3, off);
        }
        if (lane == 0) {
            g_ctx[(size_t)0*CTXD + h*DV + d] = p0;
            g_ctx[(size_t)1*CTXD + h*DV + d] = p1;
            g_ctx[(size_t)2*CTXD + h*DV + d] = p2;
            g_ctx[(size_t)3*CTXD + h*DV + d] = p3;
        }
    }
}

// ---------------- host launch (single stream, zero allocations) ----------------
extern "C" void kernel_launch(void* const* d_in, const int* in_sizes, int n_in,
                              void* d_out, int out_size)
{
    const float* x      = (const float*)d_in[0];
    const float* mask   = (const float*)d_in[1];
    const int*   posw   = (const int*)  d_in[2];
    const float* past   = (const float*)d_in[3];
    const float* cosT   = (const float*)d_in[4];
    const float* sinT   = (const float*)d_in[5];
    const float* w_qa   = (const float*)d_in[6];
    const float* gq     = (const float*)d_in[7];
    const float* w_qb   = (const float*)d_in[8];
    const float* w_kva  = (const float*)d_in[9];
    const float* gkv    = (const float*)d_in[10];
    const float* w_kvb  = (const float*)d_in[11];
    const float* w_o    = (const float*)d_in[12];

    float* out_attn  = (float*)d_out;                  // [4,1,7168]
    float* out_cache = out_attn + (size_t)BB*HID;      // [4,1025,576]

    float *p_qa, *p_qan, *p_q, *p_ckv, *p_ctx;
    cudaGetSymbolAddress((void**)&p_qa,  g_qa);
    cudaGetSymbolAddress((void**)&p_qan, g_qan);
    cudaGetSymbolAddress((void**)&p_q,   g_q);
    cudaGetSymbolAddress((void**)&p_ckv, g_ckv);
    cudaGetSymbolAddress((void**)&p_ctx, g_ctx);

    // q_a = x @ w_qa.T  AND  ckv = x @ w_kva.T  (one launch, 132 blocks)
    gemv3_dual_kernel<<<(QL+QFD)/16, 256>>>((const float4*)w_qa, (const float4*)w_kva,
                                            (const float4*)x, p_qa, p_ckv, HID/4);
    // rmsnorm(q_a)
    rmsnorm_q_kernel<<<BB, 256>>>(gq);
    // q = q_an @ w_qb.T        (151 MB, 1536 blocks)
    gemv3_kernel<<<QROWS/16, 256>>>((const float4*)w_qb, (const float4*)p_qan, p_q, QL/4, QROWS);
    // fused prep v3: transpose+copy (single past read) | ckv_post
    prep_kernel<<<PREP_TRANS + BB, 256>>>(past, out_cache, gkv, cosT, sinT, posw);
    // absorption v3 + fused q_pe RoPE
    absorb_rope_kernel<<<HH, 256>>>(w_kvb, cosT, sinT, posw);
    // attention: split-KV, 512 threads
    attn_split_kernel<<<dim3(HH/8, NSPLIT, BB), 512>>>(past, out_cache, mask);
    // combine + V projection
    vproj_combine_kernel<<<dim3(HH, 2), 256>>>(w_kvb);
    // attn_out = ctx @ w_o.T   (470 MB, 448 blocks)
    gemv3_kernel<<<HID/16, 256>>>((const float4*)w_o, (const float4*)p_ctx, out_attn, CTXD/4, HID);
}

// round 15
// speedup vs baseline: 1.1357x; 1.0162x over previous
#include <cuda_runtime.h>
#include <cuda_bf16.h>
#include <cstdint>

// ---------------- problem constants ----------------
#define BB 4
#define HH 128
#define HID 7168
#define QL 1536
#define KVL 512
#define DN 128
#define DR 64
#define DV 128
#define DQK 192
#define TT 1025          // PAST + 1
#define TTP 1028         // padded t-stride for g_ct (16B alignment)
#define QROWS (HH*DQK)   // 24576
#define CTXD (HH*DV)     // 16384
#define QFD 576          // KVL + DR
#define NSPLIT 4
#define SCP2 260
// 1/sqrt(192)
#define SCALE_QK 0.07216878364870323f

// ---------------- device scratch ----------------
__device__ float g_qa[BB*QL];
__device__ float g_q[BB*QROWS];
__device__ float g_ckv[BB*QFD];
__device__ float g_qfull[BB*HH*QFD];
__device__ float g_ctx[BB*CTXD];
__device__ float g_ct[(size_t)BB*QFD*TTP];    // transposed cache [b][k][t], padded
__device__ float g_pm[BB*HH*NSPLIT];
__device__ float g_ps[BB*HH*NSPLIT];
__device__ float g_pctx[(size_t)BB*HH*NSPLIT*KVL];

__device__ __forceinline__ int get_pos(const int* __restrict__ p, int b)
{
    bool is64 = (p[1] == 0) && (p[3] == 0) && (p[0] != 0);
    return is64 ? p[2*b] : p[b];
}

// ---------------- GEMV core: RW=2,U=4, smem-staged X, 8-deep LDG batch ----------------
__device__ __forceinline__ void gemv_core(const float4* __restrict__ arow0,
                                          const float4* __restrict__ arow1,
                                          const float4* __restrict__ X,
                                          float4 (*sx)[512],
                                          int K4, float acc[2][4])
{
    int tid = threadIdx.x, lane = tid & 31;
    for (int kt = 0; kt < K4; kt += 512) {
        int cur = min(512, K4 - kt);
        __syncthreads();
        for (int i = tid; i < cur; i += 256) {
            sx[0][i] = X[(size_t)0*K4 + kt + i];
            sx[1][i] = X[(size_t)1*K4 + kt + i];
            sx[2][i] = X[(size_t)2*K4 + kt + i];
            sx[3][i] = X[(size_t)3*K4 + kt + i];
        }
        __syncthreads();
        for (int ib = 0; ib < cur; ib += 128) {
            float4 av[4][2];
            #pragma unroll
            for (int u = 0; u < 4; u++) {
                av[u][0] = arow0[kt + ib + u*32 + lane];
                av[u][1] = arow1[kt + ib + u*32 + lane];
            }
            #pragma unroll
            for (int u = 0; u < 4; u++) {
                #pragma unroll
                for (int b = 0; b < 4; b++) {
                    float4 xv = sx[b][ib + u*32 + lane];
                    acc[0][b] += av[u][0].x*xv.x + av[u][0].y*xv.y
                               + av[u][0].z*xv.z + av[u][0].w*xv.w;
                    acc[1][b] += av[u][1].x*xv.x + av[u][1].y*xv.y
                               + av[u][1].z*xv.z + av[u][1].w*xv.w;
                }
            }
        }
    }
    #pragma unroll
    for (int r = 0; r < 2; r++)
        #pragma unroll
        for (int b = 0; b < 4; b++)
            #pragma unroll
            for (int off = 16; off; off >>= 1)
                acc[r][b] += __shfl_xor_sync(0xffffffffu, acc[r][b], off);
}

__global__ __launch_bounds__(256, 4)
void gemv3_kernel(const float4* __restrict__ A, const float4* __restrict__ X,
                  float* __restrict__ out, int K4, int outStride)
{
    __shared__ float4 sx[4][512];
    int tid = threadIdx.x, w = tid >> 5, lane = tid & 31;
    int row0 = (blockIdx.x * 8 + w) * 2;
    float acc[2][4] = {{0,0,0,0},{0,0,0,0}};
    gemv_core(A + (size_t)row0*K4, A + (size_t)(row0+1)*K4, X, sx, K4, acc);
    if (lane == 0) {
        #pragma unroll
        for (int r = 0; r < 2; r++)
            #pragma unroll
            for (int b = 0; b < 4; b++)
                out[(size_t)b*outStride + row0 + r] = acc[r][b];
    }
}

// dual: rows [0,QL) -> A1/out1, rows [QL,QL+QFD) -> A2/out2 (same X, same K4)
__global__ __launch_bounds__(256, 4)
void gemv3_dual_kernel(const float4* __restrict__ A1, const float4* __restrict__ A2,
                       const float4* __restrict__ X,
                       float* __restrict__ out1, float* __restrict__ out2, int K4)
{
    __shared__ float4 sx[4][512];
    int tid = threadIdx.x, w = tid >> 5, lane = tid & 31;
    int row0 = (blockIdx.x * 8 + w) * 2;
    const float4* A;
    float* out;
    int outStride, rbase;
    if (row0 < QL) { A = A1; out = out1; outStride = QL; rbase = row0; }
    else           { A = A2; out = out2; outStride = QFD; rbase = row0 - QL; }
    float acc[2][4] = {{0,0,0,0},{0,0,0,0}};
    gemv_core(A + (size_t)rbase*K4, A + (size_t)(rbase+1)*K4, X, sx, K4, acc);
    if (lane == 0) {
        #pragma unroll
        for (int r = 0; r < 2; r++)
            #pragma unroll
            for (int b = 0; b < 4; b++)
                out[(size_t)b*outStride + rbase + r] = acc[r][b];
    }
}

// ---------------- w_qb GEMV with fused rmsnorm (K = 1536 fits one smem tile) ----------------
__global__ __launch_bounds__(256, 4)
void wqb_kernel(const float4* __restrict__ A, const float4* __restrict__ X,
                const float4* __restrict__ gamma4, float* __restrict__ out)
{
    const int K4 = QL/4;   // 384
    __shared__ float4 sx[4][QL/4];
    __shared__ float red[4][8];
    __shared__ float srs[4];
    int tid = threadIdx.x, w = tid >> 5, lane = tid & 31;

    // stage raw q_a
    for (int i = tid; i < K4; i += 256) {
        sx[0][i] = X[(size_t)0*K4 + i];
        sx[1][i] = X[(size_t)1*K4 + i];
        sx[2][i] = X[(size_t)2*K4 + i];
        sx[3][i] = X[(size_t)3*K4 + i];
    }
    __syncthreads();
    // block-local sum of squares per batch
    float ss[4] = {0.f, 0.f, 0.f, 0.f};
    for (int i = tid; i < K4; i += 256) {
        #pragma unroll
        for (int b = 0; b < 4; b++) {
            float4 v = sx[b][i];
            ss[b] += v.x*v.x + v.y*v.y + v.z*v.z + v.w*v.w;
        }
    }
    #pragma unroll
    for (int b = 0; b < 4; b++)
        #pragma unroll
        for (int off = 16; off; off >>= 1)
            ss[b] += __shfl_xor_sync(0xffffffffu, ss[b], off);
    if (lane == 0) {
        #pragma unroll
        for (int b = 0; b < 4; b++) red[b][w] = ss[b];
    }
    __syncthreads();
    if (tid < 4) {
        float t = 0.f;
        #pragma unroll
        for (int i = 0; i < 8; i++) t += red[tid][i];
        srs[tid] = rsqrtf(t / (float)QL + 1e-6f);
    }
    __syncthreads();
    // normalize in smem with gamma
    {
        float rs0 = srs[0], rs1 = srs[1], rs2 = srs[2], rs3 = srs[3];
        for (int i = tid; i < K4; i += 256) {
            float4 g = gamma4[i];
            float4 v;
            v = sx[0][i]; sx[0][i] = make_float4(v.x*rs0*g.x, v.y*rs0*g.y, v.z*rs0*g.z, v.w*rs0*g.w);
            v = sx[1][i]; sx[1][i] = make_float4(v.x*rs1*g.x, v.y*rs1*g.y, v.z*rs1*g.z, v.w*rs1*g.w);
            v = sx[2][i]; sx[2][i] = make_float4(v.x*rs2*g.x, v.y*rs2*g.y, v.z*rs2*g.z, v.w*rs2*g.w);
            v = sx[3][i]; sx[3][i] = make_float4(v.x*rs3*g.x, v.y*rs3*g.y, v.z*rs3*g.z, v.w*rs3*g.w);
        }
    }
    __syncthreads();
    // gemv inner loop (single tile)
    int row0 = (blockIdx.x * 8 + w) * 2;
    const float4* arow0 = A + (size_t)row0 * K4;
    const float4* arow1 = arow0 + K4;
    float acc[2][4] = {{0,0,0,0},{0,0,0,0}};
    for (int ib = 0; ib < K4; ib += 128) {
        float4 av[4][2];
        #pragma unroll
        for (int u = 0; u < 4; u++) {
            av[u][0] = arow0[ib + u*32 + lane];
            av[u][1] = arow1[ib + u*32 + lane];
        }
        #pragma unroll
        for (int u = 0; u < 4; u++) {
            #pragma unroll
            for (int b = 0; b < 4; b++) {
                float4 xv = sx[b][ib + u*32 + lane];
                acc[0][b] += av[u][0].x*xv.x + av[u][0].y*xv.y
                           + av[u][0].z*xv.z + av[u][0].w*xv.w;
                acc[1][b] += av[u][1].x*xv.x + av[u][1].y*xv.y
                           + av[u][1].z*xv.z + av[u][1].w*xv.w;
            }
        }
    }
    #pragma unroll
    for (int r = 0; r < 2; r++)
        #pragma unroll
        for (int b = 0; b < 4; b++)
            #pragma unroll
            for (int off = 16; off; off >>= 1)
                acc[r][b] += __shfl_xor_sync(0xffffffffu, acc[r][b], off);
    if (lane == 0) {
        #pragma unroll
        for (int r = 0; r < 2; r++)
            #pragma unroll
            for (int b = 0; b < 4; b++)
                out[(size_t)b*QROWS + row0 + r] = acc[r][b];
    }
}

// ---------------- fused prep+absorb: transpose+copy | ckv_post | absorb ----------------
// blocks [0,576): transpose+copy; [576,580): ckv_post; [580,708): absorb head h=blk-580
#define PREP_TRANS 576
#define PREP_TOTAL (PREP_TRANS + BB + HH)
__global__ __launch_bounds__(256)
void prep_absorb_kernel(const float* __restrict__ past,
                        float* __restrict__ out_cache,
                        const float* __restrict__ gkv, const float* __restrict__ cosT,
                        const float* __restrict__ sinT, const int* __restrict__ posw,
                        const float* __restrict__ w_kvb)
{
    __shared__ __align__(16) float smu[64*68];
    int blk = blockIdx.x, tid = threadIdx.x;

    if (blk < PREP_TRANS) {
        float (*tile)[68] = (float(*)[68])smu;
        int b = blk / 144, rem = blk % 144;
        int kb = (rem / 16) * 64, tb = (rem % 16) * 64;
        int tx = tid & 15, ty = tid >> 4;   // 16 x 16
        #pragma unroll
        for (int j = 0; j < 4; j++) {
            int t = tb + ty + 16*j;
            float4 v = *(const float4*)&past[((size_t)b*(TT-1) + t)*QFD + kb + tx*4];
            *(float4*)&tile[ty + 16*j][tx*4] = v;
            *(float4*)&out_cache[((size_t)b*TT + t)*QFD + kb + tx*4] = v;   // fused copy
        }
        __syncthreads();
        #pragma unroll
        for (int j = 0; j < 4; j++) {
            int k = ty + 16*j;
            float4 o;
            o.x = tile[tx*4+0][k];
            o.y = tile[tx*4+1][k];
            o.z = tile[tx*4+2][k];
            o.w = tile[tx*4+3][k];
            *(float4*)&g_ct[((size_t)b*QFD + kb + k)*TTP + tb + tx*4] = o;
        }
        return;
    }
    if (blk < PREP_TRANS + BB) {
        int b = blk - PREP_TRANS;
        float* red = smu;
        float* prs = smu + 8;
        const float* cv = g_ckv + b*QFD;
        float ss = 0.f;
        for (int i = tid; i < KVL; i += 256) { float v = cv[i]; ss += v*v; }
        #pragma unroll
        for (int off = 16; off; off >>= 1) ss += __shfl_xor_sync(0xffffffffu, ss, off);
        if ((tid & 31) == 0) red[tid >> 5] = ss;
        __syncthreads();
        if (tid == 0) {
            float t = 0.f;
            #pragma unroll
            for (int i = 0; i < 8; i++) t += red[i];
            *prs = rsqrtf(t / (float)KVL + 1e-6f);
        }
        __syncthreads();
        float s_rs = *prs;
        float* dst = out_cache + ((size_t)b*TT + (TT-1)) * QFD;
        float* ctb = g_ct + (size_t)b*QFD*TTP + (TT-1);
        for (int i = tid; i < KVL; i += 256) {
            float v = cv[i] * s_rs * gkv[i];
            dst[i] = v;
            ctb[(size_t)i*TTP] = v;
        }
        if (tid < DR) {
            int d = tid;
            int p = get_pos(posw, b);
            float v  = cv[KVL + d];
            float pr = (d < 32) ? -cv[KVL + d + 32] : cv[KVL + d - 32];
            float res = v * cosT[(size_t)p*DR + d] + pr * sinT[(size_t)p*DR + d];
            dst[KVL + d] = res;
            ctb[(size_t)(KVL + d)*TTP] = res;
        }
        return;
    }
    // ---- absorb for head h ----
    {
        int h = blk - (PREP_TRANS + BB);
        float* qs = smu;                       // [4][128]
        float4* sred = (float4*)(smu + 512);   // [4][128] float4
        int c4 = tid & 127, dh = tid >> 7;
        for (int i = tid; i < 4*DN; i += 256) {
            int b = i >> 7, d = i & 127;
            qs[b*DN + d] = g_q[(size_t)b*QROWS + h*DQK + d];
        }
        __syncthreads();
        float4 acc[4];
        #pragma unroll
        for (int b = 0; b < 4; b++) acc[b] = make_float4(0.f, 0.f, 0.f, 0.f);
        const float4* wk4 = (const float4*)(w_kvb + (size_t)h*256*KVL) + c4;
        int d0base = dh * 64;
        for (int d0 = d0base; d0 < d0base + 64; d0 += 8) {
            float4 wv[8];
            #pragma unroll
            for (int u = 0; u < 8; u++) wv[u] = wk4[(size_t)(d0+u)*128];
            #pragma unroll
            for (int u = 0; u < 8; u++) {
                #pragma unroll
                for (int b = 0; b < 4; b++) {
                    float q = qs[b*DN + d0+u];
                    acc[b].x += q*wv[u].x; acc[b].y += q*wv[u].y;
                    acc[b].z += q*wv[u].z; acc[b].w += q*wv[u].w;
                }
            }
        }
        if (dh == 1) {
            #pragma unroll
            for (int b = 0; b < 4; b++) sred[b*128 + c4] = acc[b];
        }
        __syncthreads();
        if (dh == 0) {
            #pragma unroll
            for (int b = 0; b < 4; b++) {
                float4 o = sred[b*128 + c4];
                o.x = (acc[b].x + o.x) * SCALE_QK;
                o.y = (acc[b].y + o.y) * SCALE_QK;
                o.z = (acc[b].z + o.z) * SCALE_QK;
                o.w = (acc[b].w + o.w) * SCALE_QK;
                *(float4*)&g_qfull[((size_t)(b*HH + h))*QFD + c4*4] = o;
            }
        }
        if (tid < 4*DR) {
            int b = tid >> 6, d = tid & 63;
            int p = get_pos(posw, b);
            const float* qp = g_q + (size_t)b*QROWS + h*DQK + DN;
            float v  = qp[d];
            float pr = (d < 32) ? -qp[d+32] : qp[d-32];
            g_qfull[((size_t)(b*HH + h))*QFD + KVL + d] =
                (v * cosT[(size_t)p*DR + d] + pr * sinT[(size_t)p*DR + d]) * SCALE_QK;
        }
    }
}

// ---------------- attention split, 512 threads ----------------
__global__ __launch_bounds__(512)
void attn_split_kernel(const float* __restrict__ past,
                       const float* __restrict__ out_cache,
                       const float* __restrict__ mask)
{
    __shared__ __align__(16) float qsm[8*QFD];
    __shared__ __align__(16) float sc[8*SCP2];
    int b = blockIdx.z, split = blockIdx.y, h0 = blockIdx.x * 8, tid = threadIdx.x;
    int T0 = split * 256;
    int TE = (split == NSPLIT-1) ? TT : T0 + 256;
    int cnt = TE - T0;

    for (int i = tid; i < 8*QFD; i += 512) {
        int h = i / QFD, k = i % QFD;
        qsm[i] = g_qfull[((size_t)(b*HH + h0 + h))*QFD + k];
    }
    __syncthreads();

    // ---- phase 1: scores; half-block does 4 heads each for t = T0 + (tid&255) ----
    {
        int tq = tid & 255;
        int hb = (tid >> 8) * 4;
        float acc[4] = {0.f, 0.f, 0.f, 0.f};
        const float* ctb = g_ct + (size_t)b*QFD*TTP + T0 + tq;
        for (int k = 0; k < QFD; k += 8) {
            float c[8];
            #pragma unroll
            for (int j = 0; j < 8; j++) c[j] = ctb[(size_t)(k+j)*TTP];
            #pragma unroll
            for (int hh = 0; hh < 4; hh++) {
                const float4* qv = reinterpret_cast<const float4*>(&qsm[(hb+hh)*QFD + k]);
                float4 q0 = qv[0], q1 = qv[1];
                acc[hh] += q0.x*c[0] + q0.y*c[1] + q0.z*c[2] + q0.w*c[3]
                         + q1.x*c[4] + q1.y*c[5] + q1.z*c[6] + q1.w*c[7];
            }
        }
        float mk = mask[(size_t)b*TT + T0 + tq];
        #pragma unroll
        for (int hh = 0; hh < 4; hh++) sc[(hb+hh)*SCP2 + tq] = acc[hh] + mk;

        if (split == NSPLIT-1 && tid < 32) {   // t = 1024 by warp 0
            const float* crow = out_cache + ((size_t)b*TT + (TT-1))*QFD;
            float mk2 = mask[(size_t)b*TT + (TT-1)];
            for (int h = 0; h < 8; h++) {
                float p = 0.f;
                for (int i = tid; i < QFD; i += 32) p += qsm[h*QFD + i]*crow[i];
                #pragma unroll
                for (int off = 16; off; off >>= 1) p += __shfl_xor_sync(0xffffffffu, p, off);
                if (tid == 0) sc[h*SCP2 + 256] = p + mk2;
            }
        }
    }
    __syncthreads();

    // ---- phase 2: local softmax, warps 0-7 (one per head) ----
    if (tid < 256) {
        int w = tid >> 5, lane = tid & 31, h = w;
        float m = -1e30f;
        for (int t = lane; t < cnt; t += 32) m = fmaxf(m, sc[h*SCP2 + t]);
        #pragma unroll
        for (int off = 16; off; off >>= 1) m = fmaxf(m, __shfl_xor_sync(0xffffffffu, m, off));
        float s = 0.f;
        for (int t = lane; t < cnt; t += 32) {
            float e = __expf(sc[h*SCP2 + t] - m);
            sc[h*SCP2 + t] = e;
            s += e;
        }
        #pragma unroll
        for (int off = 16; off; off >>= 1) s += __shfl_xor_sync(0xffffffffu, s, off);
        if (lane == 0) {
            int idx = (b*HH + h0 + h)*NSPLIT + split;
            g_pm[idx] = m;
            g_ps[idx] = s;
        }
    }
    __syncthreads();

    // ---- phase 3: partial ctx; each thread owns latent column c = tid ----
    {
        float acc[8];
        #pragma unroll
        for (int h = 0; h < 8; h++) acc[h] = 0.f;
        const float* pb = past + (size_t)b*(TT-1)*QFD;
        int c = tid;
        for (int t0 = T0; t0 < T0 + 256; t0 += 4) {
            float v[4];
            #pragma unroll
            for (int j = 0; j < 4; j++) v[j] = pb[(size_t)(t0+j)*QFD + c];
            int tl = t0 - T0;
            #pragma unroll
            for (int h = 0; h < 8; h++) {
                float4 a4 = *reinterpret_cast<const float4*>(&sc[h*SCP2 + tl]);
                acc[h] += a4.x*v[0] + a4.y*v[1] + a4.z*v[2] + a4.w*v[3];
            }
        }
        if (TE == TT) {
            float v = out_cache[((size_t)b*TT + (TT-1))*QFD + c];
            #pragma unroll
            for (int h = 0; h < 8; h++) acc[h] += sc[h*SCP2 + 256] * v;
        }
        #pragma unroll
        for (int h = 0; h < 8; h++)
            g_pctx[((size_t)(b*HH + h0 + h)*NSPLIT + split)*KVL + c] = acc[h];
    }
}

// ---------------- fused combine + V projection; grid (HH, 2) ----------------
__global__ void vproj_combine_kernel(const float* __restrict__ w_kvb)
{
    __shared__ float cl[4][KVL];
    int h = blockIdx.x, half = blockIdx.y, tid = threadIdx.x;
    {
        int bq = tid >> 6, lq = tid & 63;
        int idx = bq*HH + h;
        float m = -1e30f;
        #pragma unroll
        for (int s = 0; s < NSPLIT; s++) m = fmaxf(m, g_pm[idx*NSPLIT + s]);
        float e[NSPLIT]; float ssum = 0.f;
        #pragma unroll
        for (int s = 0; s < NSPLIT; s++) {
            e[s] = __expf(g_pm[idx*NSPLIT + s] - m);
            ssum += g_ps[idx*NSPLIT + s] * e[s];
        }
        float inv = 1.0f / ssum;
        for (int c = lq; c < KVL; c += 64) {
            float acc = 0.f;
            #pragma unroll
            for (int s = 0; s < NSPLIT; s++)
                acc += g_pctx[((size_t)idx*NSPLIT + s)*KVL + c] * e[s];
            cl[bq][c] = acc * inv;
        }
    }
    __syncthreads();
    int w = tid >> 5, lane = tid & 31;
    int dv = half*64 + w*8;
    for (int d = dv; d < dv + 8; d++) {
        const float* wr = w_kvb + ((size_t)(h*256 + DN + d))*KVL;
        float p0 = 0.f, p1 = 0.f, p2 = 0.f, p3 = 0.f;
        #pragma unroll 4
        for (int i = lane; i < KVL; i += 32) {
            float wv = wr[i];
            p0 += wv * cl[0][i];
            p1 += wv * cl[1][i];
            p2 += wv * cl[2][i];
            p3 += wv * cl[3][i];
        }
        #pragma unroll
        for (int off = 16; off; off >>= 1) {
            p0 += __shfl_xor_sync(0xffffffffu, p0, off);
            p1 += __shfl_xor_sync(0xffffffffu, p1, off);
            p2 += __shfl_xor_sync(0xffffffffu, p2, off);
            p3 += __shfl_xor_sync(0xffffffffu, p3, off);
        }
        if (lane == 0) {
            g_ctx[(size_t)0*CTXD + h*DV + d] = p0;
            g_ctx[(size_t)1*CTXD + h*DV + d] = p1;
            g_ctx[(size_t)2*CTXD + h*DV + d] = p2;
            g_ctx[(size_t)3*CTXD + h*DV + d] = p3;
        }
    }
}

// ---------------- host launch (single stream, zero allocations, 6 kernels) ----------------
extern "C" void kernel_launch(void* const* d_in, const int* in_sizes, int n_in,
                              void* d_out, int out_size)
{
    const float* x      = (const float*)d_in[0];
    const float* mask   = (const float*)d_in[1];
    const int*   posw   = (const int*)  d_in[2];
    const float* past   = (const float*)d_in[3];
    const float* cosT   = (const float*)d_in[4];
    const float* sinT   = (const float*)d_in[5];
    const float* w_qa   = (const float*)d_in[6];
    const float* gq     = (const float*)d_in[7];
    const float* w_qb   = (const float*)d_in[8];
    const float* w_kva  = (const float*)d_in[9];
    const float* gkv    = (const float*)d_in[10];
    const float* w_kvb  = (const float*)d_in[11];
    const float* w_o    = (const float*)d_in[12];

    float* out_attn  = (float*)d_out;                  // [4,1,7168]
    float* out_cache = out_attn + (size_t)BB*HID;      // [4,1025,576]

    float *p_qa, *p_q, *p_ckv, *p_ctx;
    cudaGetSymbolAddress((void**)&p_qa,  g_qa);
    cudaGetSymbolAddress((void**)&p_q,   g_q);
    cudaGetSymbolAddress((void**)&p_ckv, g_ckv);
    cudaGetSymbolAddress((void**)&p_ctx, g_ctx);

    // 1) q_a = x @ w_qa.T  AND  ckv = x @ w_kva.T
    gemv3_dual_kernel<<<(QL+QFD)/16, 256>>>((const float4*)w_qa, (const float4*)w_kva,
                                            (const float4*)x, p_qa, p_ckv, HID/4);
    // 2) q = rmsnorm(q_a)*gamma @ w_qb.T  (fused rmsnorm)
    wqb_kernel<<<QROWS/16, 256>>>((const float4*)w_qb, (const float4*)p_qa,
                                  (const float4*)gq, p_q);
    // 3) fused: transpose+copy | ckv_post | absorb+RoPE
    prep_absorb_kernel<<<PREP_TOTAL, 256>>>(past, out_cache, gkv, cosT, sinT, posw, w_kvb);
    // 4) attention: split-KV, 512 threads
    attn_split_kernel<<<dim3(HH/8, NSPLIT, BB), 512>>>(past, out_cache, mask);
    // 5) combine + V projection
    vproj_combine_kernel<<<dim3(HH, 2), 256>>>(w_kvb);
    // 6) attn_out = ctx @ w_o.T   (470 MB)
    gemv3_kernel<<<HID/16, 256>>>((const float4*)w_o, (const float4*)p_ctx, out_attn, CTXD/4, HID);
}